// round 1
// baseline (speedup 1.0000x reference)
#include <cuda_runtime.h>
#include <math.h>

#define NN 100000
#define EE 1600000
#define DIN 128
#define DH  256

// ---- device scratch (allocation-free contract: __device__ globals) ----
__device__ float g_agg[2ull * NN * DIN];   // agg rows 0..N-1 from x, N..2N-1 from x_tilde (102.4 MB)
__device__ float g_h[2ull * NN * DH];      // h rows 0..N-1, h_tilde rows N..2N-1 (204.8 MB)
__device__ float g_colsum[DH];
__device__ float g_v[DH];
__device__ float g_W1t[DIN * DH];          // W1 transposed: [k][j]
__device__ int   g_rowptr[NN + 1];

// ------------------------------------------------------------------
__global__ void k_init() {
    int t = threadIdx.x;
    if (t < DH) g_colsum[t] = 0.0f;
}

// W1 [DH][DIN] -> W1t [DIN][DH]
__global__ void k_transpose(const float* __restrict__ W1) {
    int idx = blockIdx.x * blockDim.x + threadIdx.x;
    if (idx < DIN * DH) {
        int k = idx / DH, j = idx % DH;
        g_W1t[idx] = W1[j * DIN + k];
    }
}

// rowptr from sorted adj_row
__global__ void k_rowptr(const int* __restrict__ adj_row) {
    int e = blockIdx.x * blockDim.x + threadIdx.x;
    if (e >= EE) return;
    int r  = adj_row[e];
    int rp = (e == 0) ? -1 : adj_row[e - 1];
    for (int k = rp + 1; k <= r; k++) g_rowptr[k] = e;
    if (e == EE - 1) {
        for (int k = r + 1; k <= NN; k++) g_rowptr[k] = EE;
    }
}

// ------------------------------------------------------------------
// SpMM: one warp per row, both features in one pass (shared index loads).
__global__ void k_spmm(const float4* __restrict__ x4, const float4* __restrict__ xt4,
                       const float* __restrict__ vals, const int* __restrict__ cols) {
    int w    = (blockIdx.x * blockDim.x + threadIdx.x) >> 5;
    int lane = threadIdx.x & 31;
    if (w >= NN) return;
    int e0 = g_rowptr[w], e1 = g_rowptr[w + 1];
    float4 a = make_float4(0.f, 0.f, 0.f, 0.f);
    float4 b = make_float4(0.f, 0.f, 0.f, 0.f);
    int e = e0;
    for (; e + 1 < e1; e += 2) {
        float w0 = __ldg(vals + e);
        float w1 = __ldg(vals + e + 1);
        int   c0 = __ldg(cols + e);
        int   c1 = __ldg(cols + e + 1);
        float4 x0 = x4[c0 * 32 + lane];
        float4 t0 = xt4[c0 * 32 + lane];
        float4 x1 = x4[c1 * 32 + lane];
        float4 t1 = xt4[c1 * 32 + lane];
        a.x += w0 * x0.x; a.y += w0 * x0.y; a.z += w0 * x0.z; a.w += w0 * x0.w;
        b.x += w0 * t0.x; b.y += w0 * t0.y; b.z += w0 * t0.z; b.w += w0 * t0.w;
        a.x += w1 * x1.x; a.y += w1 * x1.y; a.z += w1 * x1.z; a.w += w1 * x1.w;
        b.x += w1 * t1.x; b.y += w1 * t1.y; b.z += w1 * t1.z; b.w += w1 * t1.w;
    }
    if (e < e1) {
        float w0 = __ldg(vals + e);
        int   c0 = __ldg(cols + e);
        float4 x0 = x4[c0 * 32 + lane];
        float4 t0 = xt4[c0 * 32 + lane];
        a.x += w0 * x0.x; a.y += w0 * x0.y; a.z += w0 * x0.z; a.w += w0 * x0.w;
        b.x += w0 * t0.x; b.y += w0 * t0.y; b.z += w0 * t0.z; b.w += w0 * t0.w;
    }
    float4* agg4 = (float4*)g_agg;
    agg4[(size_t)w * 32 + lane]              = a;
    agg4[((size_t)NN + w) * 32 + lane]       = b;
}

// ------------------------------------------------------------------
// GEMM: h = PReLU(agg @ W1^T), fused column-sum of h (rows < NN only).
// Block tile: 128 rows x 256 cols, K=128 (single stage).
// 256 threads (tx 0..15, ty 0..15): each thread 8 rows x 16 cols as f32x2 pairs.
__global__ void __launch_bounds__(256, 1) k_gemm(const float* __restrict__ prelu_a) {
    extern __shared__ float smem[];
    float* As = smem;               // [128][DIN]
    float* Bs = smem + 128 * DIN;   // [DIN][DH]
    int tid = threadIdx.x;
    int tx = tid & 15, ty = tid >> 4;
    long rowBase = (long)blockIdx.x * 128;
    const long totalRows = 2L * NN;

    // Load Bs (straight copy of W1t, coalesced, conflict-free)
    {
        const float4* src = (const float4*)g_W1t;
        float4* dst = (float4*)Bs;
#pragma unroll
        for (int i = 0; i < 32; i++) dst[tid + i * 256] = src[tid + i * 256];
    }
    // Load As (row-major copy, zero-fill OOB)
    {
        const float4* src = (const float4*)g_agg;
        float4* dst = (float4*)As;
#pragma unroll
        for (int i = 0; i < 16; i++) {
            int idx = tid + i * 256;
            long row = rowBase + (idx >> 5);
            float4 v = make_float4(0.f, 0.f, 0.f, 0.f);
            if (row < totalRows) v = src[row * 32 + (idx & 31)];
            dst[idx] = v;
        }
    }
    __syncthreads();

    float pa = prelu_a[0];
    float csum[16];
#pragma unroll
    for (int i = 0; i < 16; i++) csum[i] = 0.f;

#pragma unroll
    for (int gpass = 0; gpass < 2; gpass++) {
        unsigned long long acc[8][4];
#pragma unroll
        for (int m = 0; m < 8; m++)
#pragma unroll
            for (int p = 0; p < 4; p++) acc[m][p] = 0ull;
        int jbase0 = tx * 4 + (gpass * 2 + 0) * 64;
        int jbase1 = tx * 4 + (gpass * 2 + 1) * 64;
#pragma unroll 4
        for (int k = 0; k < DIN; k++) {
            unsigned long long ap[8];
#pragma unroll
            for (int m = 0; m < 8; m++) {
                float a = As[(ty * 8 + m) * DIN + k];
                asm("mov.b64 %0, {%1, %1};" : "=l"(ap[m]) : "f"(a));
            }
            ulonglong2 b0 = *(const ulonglong2*)(Bs + k * DH + jbase0);
            ulonglong2 b1 = *(const ulonglong2*)(Bs + k * DH + jbase1);
#pragma unroll
            for (int m = 0; m < 8; m++) {
                asm("fma.rn.f32x2 %0, %1, %2, %0;" : "+l"(acc[m][0]) : "l"(ap[m]), "l"(b0.x));
                asm("fma.rn.f32x2 %0, %1, %2, %0;" : "+l"(acc[m][1]) : "l"(ap[m]), "l"(b0.y));
                asm("fma.rn.f32x2 %0, %1, %2, %0;" : "+l"(acc[m][2]) : "l"(ap[m]), "l"(b1.x));
                asm("fma.rn.f32x2 %0, %1, %2, %0;" : "+l"(acc[m][3]) : "l"(ap[m]), "l"(b1.y));
            }
        }
        // Epilogue: unpack, PReLU, store h, accumulate column partial sums
#pragma unroll
        for (int m = 0; m < 8; m++) {
            long row = rowBase + ty * 8 + m;
            if (row < totalRows) {
                float z[8];
#pragma unroll
                for (int p = 0; p < 4; p++) {
                    float lo, hi;
                    asm("mov.b64 {%0, %1}, %2;" : "=f"(lo), "=f"(hi) : "l"(acc[m][p]));
                    z[p * 2] = lo; z[p * 2 + 1] = hi;
                }
#pragma unroll
                for (int q = 0; q < 8; q++) z[q] = (z[q] >= 0.f) ? z[q] : pa * z[q];
                float4* hp = (float4*)(g_h + row * DH);
                hp[jbase0 >> 2] = make_float4(z[0], z[1], z[2], z[3]);
                hp[jbase1 >> 2] = make_float4(z[4], z[5], z[6], z[7]);
                if (row < NN) {
#pragma unroll
                    for (int q = 0; q < 8; q++) csum[gpass * 8 + q] += z[q];
                }
            }
        }
    }

    // Column-sum reduction: red[j][ty] in smem, then 256 global atomics.
    __syncthreads();
    float* red = smem;  // DH*16 floats = 16 KB, reuses As
#pragma unroll
    for (int s = 0; s < 16; s++) {
        int gp = s >> 3, q = s & 7;
        int j = tx * 4 + (gp * 2 + (q >> 2)) * 64 + (q & 3);
        red[j * 16 + ty] = csum[s];
    }
    __syncthreads();
    if (tid < DH) {
        float t = 0.f;
#pragma unroll
        for (int u = 0; u < 16; u++) t += red[tid * 16 + u];
        atomicAdd(&g_colsum[tid], t);
    }
}

// ------------------------------------------------------------------
// s = sigmoid(colsum/N); v = w_bil @ s
__global__ void k_sv(const float* __restrict__ w_bil) {
    __shared__ float s[DH];
    int t = threadIdx.x;
    float m = g_colsum[t] / (float)NN;
    s[t] = 1.f / (1.f + expf(-m));
    __syncthreads();
    float acc = 0.f;
#pragma unroll 8
    for (int j = 0; j < DH; j++) acc += w_bil[t * DH + j] * s[j];
    g_v[t] = acc;
}

// ------------------------------------------------------------------
// out[row] = dot(h[row], v) for row in [0, 2N): dp then dn, matching concat order.
__global__ void k_dot(float* __restrict__ out) {
    __shared__ float vs[DH];
    if (threadIdx.x < DH) vs[threadIdx.x] = g_v[threadIdx.x];
    __syncthreads();
    int w    = (blockIdx.x * blockDim.x + threadIdx.x) >> 5;
    int lane = threadIdx.x & 31;
    if (w >= 2 * NN) return;
    const float4* h4 = (const float4*)(g_h + (size_t)w * DH);
    const float4* v4 = (const float4*)vs;
    float4 hA = h4[lane], hB = h4[lane + 32];
    float4 vA = v4[lane], vB = v4[lane + 32];
    float acc = hA.x * vA.x + hA.y * vA.y + hA.z * vA.z + hA.w * vA.w
              + hB.x * vB.x + hB.y * vB.y + hB.z * vB.z + hB.w * vB.w;
#pragma unroll
    for (int o = 16; o > 0; o >>= 1) acc += __shfl_xor_sync(0xffffffffu, acc, o);
    if (lane == 0) out[w] = acc;
}

// ------------------------------------------------------------------
extern "C" void kernel_launch(void* const* d_in, const int* in_sizes, int n_in,
                              void* d_out, int out_size) {
    const float* x       = (const float*)d_in[0];
    const float* x_tilde = (const float*)d_in[1];
    const float* vals    = (const float*)d_in[2];
    const int*   adj_row = (const int*)d_in[3];
    const int*   adj_col = (const int*)d_in[4];
    const float* W1      = (const float*)d_in[5];
    const float* prelu_a = (const float*)d_in[6];
    const float* w_bil   = (const float*)d_in[7];
    float* out = (float*)d_out;

    cudaFuncSetAttribute(k_gemm, cudaFuncAttributeMaxDynamicSharedMemorySize, 196608);

    k_init<<<1, 256>>>();
    k_transpose<<<(DIN * DH + 255) / 256, 256>>>(W1);
    k_rowptr<<<(EE + 255) / 256, 256>>>(adj_row);
    k_spmm<<<(NN * 32) / 256, 256>>>((const float4*)x, (const float4*)x_tilde, vals, adj_col);
    k_gemm<<<(2 * NN + 127) / 128, 256, 196608>>>(prelu_a);
    k_sv<<<1, DH>>>(w_bil);
    k_dot<<<(2 * NN * 32 + 255) / 256, 256>>>(out);
}